// round 14
// baseline (speedup 1.0000x reference)
#include <cuda_runtime.h>
#include <math.h>

#define N_NODES 65536
#define N_EDGES 524288
#define N_GRAPHS 64
#define PTS 1024
#define FMAX 512

// ---------------- scratch (device globals: no allocation allowed) ----------
__device__ float g_bufA[(size_t)N_NODES * FMAX];
__device__ float g_bufB[(size_t)N_NODES * FMAX];
__device__ float g_bufC[(size_t)N_NODES * FMAX];
__device__ float g_dinv[N_NODES];
__device__ int   g_cnt[N_NODES];
__device__ int   g_cursor[N_NODES];
__device__ int   g_tmp[N_NODES];
__device__ int   g_bsum[64];
__device__ int   g_boff[64];
__device__ int   g_rowptr[N_NODES + 1];
__device__ int   g_csrc[N_EDGES];
__device__ float g_ccoef[N_EDGES];
__device__ float g_h[N_GRAPHS * 1024];
__device__ float g_h2[N_GRAPHS * 512];

// ---------------- counters / normalization ---------------------------------
__global__ void k_zero2(int* cnt, int* cursor) {
    int i = blockIdx.x * blockDim.x + threadIdx.x;
    if (i < N_NODES) { cnt[i] = 0; cursor[i] = 0; }
}

__global__ void k_count(const int* __restrict__ ei, int* __restrict__ cnt) {
    int e = blockIdx.x * blockDim.x + threadIdx.x;
    if (e < N_EDGES) atomicAdd(&cnt[ei[N_EDGES + e]], 1);
}

__global__ void k_dinv(const int* __restrict__ cnt, float* __restrict__ dinv) {
    int i = blockIdx.x * blockDim.x + threadIdx.x;
    if (i < N_NODES) dinv[i] = rsqrtf((float)(cnt[i] + 1));   // +1 self-loop
}

// ---------------- exclusive scan of cnt -> rowptr ---------------------------
__global__ void k_scan1(const int* __restrict__ cnt, int* __restrict__ tmp,
                        int* __restrict__ bsum) {
    __shared__ int s[1024];
    int t = threadIdx.x;
    int i = blockIdx.x * 1024 + t;
    s[t] = cnt[i];
    __syncthreads();
    for (int off = 1; off < 1024; off <<= 1) {
        int x = (t >= off) ? s[t - off] : 0;
        __syncthreads();
        s[t] += x;
        __syncthreads();
    }
    tmp[i] = s[t];
    if (t == 1023) bsum[blockIdx.x] = s[t];
}

__global__ void k_scan2(const int* __restrict__ bsum, int* __restrict__ boff) {
    __shared__ int s[64];
    int t = threadIdx.x;
    s[t] = bsum[t];
    __syncthreads();
    for (int off = 1; off < 64; off <<= 1) {
        int x = (t >= off) ? s[t - off] : 0;
        __syncthreads();
        s[t] += x;
        __syncthreads();
    }
    boff[t] = (t == 0) ? 0 : s[t - 1];
}

__global__ void k_scan3(const int* __restrict__ tmp, const int* __restrict__ boff,
                        int* __restrict__ rowptr) {
    int i = blockIdx.x * blockDim.x + threadIdx.x;
    if (i < N_NODES) {
        rowptr[i + 1] = tmp[i] + boff[i >> 10];
        if (i == 0) rowptr[0] = 0;
    }
}

__global__ void k_fill(const int* __restrict__ ei, const float* __restrict__ dinv,
                       const int* __restrict__ rowptr, int* __restrict__ cursor,
                       int* __restrict__ csrc, float* __restrict__ ccoef) {
    int e = blockIdx.x * blockDim.x + threadIdx.x;
    if (e >= N_EDGES) return;
    int r = ei[e];
    int c = ei[N_EDGES + e];
    int slot = rowptr[c] + atomicAdd(&cursor[c], 1);
    csrc[slot] = r;
    ccoef[slot] = dinv[r] * dinv[c];
}

// ---------------- CSR aggregations ------------------------------------------
__global__ void k_agg3(const int* __restrict__ rowptr, const int* __restrict__ csrc,
                       const float* __restrict__ ccoef, const float* __restrict__ x,
                       const float* __restrict__ dinv, float* __restrict__ y) {
    int i = blockIdx.x * blockDim.x + threadIdx.x;
    if (i >= N_NODES) return;
    float d = dinv[i];
    float d2 = d * d;
    float a0 = x[i * 3 + 0] * d2, a1 = x[i * 3 + 1] * d2, a2 = x[i * 3 + 2] * d2;
    int beg = rowptr[i], end = rowptr[i + 1];
    for (int j = beg; j < end; j++) {
        int s = csrc[j];
        float w = ccoef[j];
        a0 += x[s * 3 + 0] * w;
        a1 += x[s * 3 + 1] * w;
        a2 += x[s * 3 + 2] * w;
    }
    y[i * 3 + 0] = a0;
    y[i * 3 + 1] = a1;
    y[i * 3 + 2] = a2;
}

__global__ void k_agg64(const int* __restrict__ rowptr, const int* __restrict__ csrc,
                        const float* __restrict__ ccoef, const float* __restrict__ xw,
                        const float* __restrict__ dinv, float* __restrict__ out) {
    int w = (blockIdx.x * blockDim.x + threadIdx.x) >> 5;
    int lane = threadIdx.x & 31;
    if (w >= N_NODES) return;
    float d = dinv[w];
    float d2 = d * d;
    float2 a = ((const float2*)&xw[(size_t)w * 64])[lane];
    a.x *= d2; a.y *= d2;
    int beg = rowptr[w], end = rowptr[w + 1];
    for (int j = beg; j < end; j++) {
        int s = csrc[j];
        float c = ccoef[j];
        float2 v = ((const float2*)&xw[(size_t)s * 64])[lane];
        a.x += v.x * c;
        a.y += v.y * c;
    }
    ((float2*)&out[(size_t)w * 64])[lane] = a;
}

__global__ void k_agg256(const int* __restrict__ rowptr, const int* __restrict__ csrc,
                         const float* __restrict__ ccoef, const float* __restrict__ xw,
                         const float* __restrict__ dinv, float* __restrict__ out) {
    int w = (blockIdx.x * blockDim.x + threadIdx.x) >> 5;
    int lane = threadIdx.x & 31;
    if (w >= N_NODES) return;
    float d = dinv[w];
    float d2 = d * d;
    const float4* selfrow = (const float4*)&xw[(size_t)w * 256];
    float4 a0 = selfrow[lane];
    float4 a1 = selfrow[lane + 32];
    a0.x *= d2; a0.y *= d2; a0.z *= d2; a0.w *= d2;
    a1.x *= d2; a1.y *= d2; a1.z *= d2; a1.w *= d2;
    int beg = rowptr[w], end = rowptr[w + 1];
    for (int j = beg; j < end; j++) {
        int s = csrc[j];
        float c = ccoef[j];
        const float4* row = (const float4*)&xw[(size_t)s * 256];
        float4 v0 = row[lane];
        float4 v1 = row[lane + 32];
        a0.x += v0.x * c; a0.y += v0.y * c; a0.z += v0.z * c; a0.w += v0.w * c;
        a1.x += v1.x * c; a1.y += v1.y * c; a1.z += v1.z * c; a1.w += v1.w * c;
    }
    float4* o = (float4*)&out[(size_t)w * 256];
    o[lane] = a0;
    o[lane + 32] = a1;
}

// ---------------- layer-1 GEMM (K=3, N=64) ----------------------------------
__global__ void k_gemm1(const float* __restrict__ y0, const float* __restrict__ W,
                        const float* __restrict__ bias, float* __restrict__ x1) {
    __shared__ float Ws[192];
    __shared__ float bs[64];
    int t = threadIdx.x;
    if (t < 192) Ws[t] = W[t];
    if (t < 64) bs[t] = bias[t];
    __syncthreads();
    int idx = blockIdx.x * blockDim.x + t;
    int i = idx >> 6;
    int j = idx & 63;
    float a0 = y0[i * 3 + 0], a1 = y0[i * 3 + 1], a2 = y0[i * 3 + 2];
    float v = a0 * Ws[j] + a1 * Ws[64 + j] + a2 * Ws[128 + j] + bs[j];
    x1[idx] = v > 0.f ? v : 0.f;
}

// ---------------- tf32 tensor-core GEMM: C = relu(A@B + bias) ---------------
// Block 128x64, BK=32, 8 warps (32x32 warp tile), mma.sync m16n8k8 tf32.
// A,B staged into SMEM in fragment-major layout (conflict-free vector LDS).
__device__ __forceinline__ unsigned f2tf32(float x) {
    unsigned r;
    asm("cvt.rna.tf32.f32 %0, %1;" : "=r"(r) : "f"(x));
    return r;
}

__global__ __launch_bounds__(256, 2)
void k_tf32gemm(const float* __restrict__ A, const float* __restrict__ Bm,
                const float* __restrict__ bias, float* __restrict__ C,
                int N, int K) {
    // AsF: [ki(4)][mi(8)][lane(32)][reg(4)]  = 16KB
    // BsF: [ki(4)][ni(8)][lane(32)][reg(2)]  =  8KB
    __shared__ __align__(16) unsigned AsF[4 * 8 * 32 * 4];
    __shared__ __align__(16) unsigned BsF[4 * 8 * 32 * 2];

    int tid = threadIdx.x;
    int lane = tid & 31;
    int warp = tid >> 5;          // 0..7
    int warpM = warp >> 1;        // 0..3
    int warpN = warp & 1;         // 0..1
    int rowBase = blockIdx.y * 128;
    int colBase = blockIdx.x * 64;

    float acc[2][4][4];
#pragma unroll
    for (int m = 0; m < 2; m++)
#pragma unroll
        for (int n = 0; n < 4; n++)
#pragma unroll
            for (int q = 0; q < 4; q++) acc[m][n][q] = 0.f;

    for (int k0 = 0; k0 < K; k0 += 32) {
        // ---- stage A tile (128x32) into fragment layout ----
#pragma unroll
        for (int i = 0; i < 4; i++) {
            int idx = tid + i * 256;           // 0..1023 float4s
            int row = idx >> 3;                // 0..127
            int k4 = (idx & 7) * 4;            // 0..28
            float4 v = *(const float4*)&A[(size_t)(rowBase + row) * K + k0 + k4];
            int mi = row >> 4, r = row & 15;
            int ki = k4 >> 3;
            int c0 = k4 & 7;                   // 0 or 4
            int reg = (r >> 3) + ((c0 >> 2) << 1);
            int lanebase = (r & 7) * 4;
            unsigned* dst = &AsF[(((ki << 3) + mi) << 7)];
            dst[(lanebase + 0) * 4 + reg] = f2tf32(v.x);
            dst[(lanebase + 1) * 4 + reg] = f2tf32(v.y);
            dst[(lanebase + 2) * 4 + reg] = f2tf32(v.z);
            dst[(lanebase + 3) * 4 + reg] = f2tf32(v.w);
        }
        // ---- stage B tile (32x64) into fragment layout ----
#pragma unroll
        for (int i = 0; i < 2; i++) {
            int idx = tid + i * 256;           // 0..511 float4s
            int krow = idx >> 4;               // 0..31
            int n4 = (idx & 15) * 4;           // 0..60
            float4 v = *(const float4*)&Bm[(size_t)(k0 + krow) * N + colBase + n4];
            int ki = krow >> 3, kin = krow & 7;
            int ni = n4 >> 3;
            int n0 = n4 & 7;                   // 0 or 4
            int reg = kin >> 2;
            int ls = kin & 3;
            unsigned* dst = &BsF[(((ki << 3) + ni) << 6)];
            dst[((n0 + 0) * 4 + ls) * 2 + reg] = f2tf32(v.x);
            dst[((n0 + 1) * 4 + ls) * 2 + reg] = f2tf32(v.y);
            dst[((n0 + 2) * 4 + ls) * 2 + reg] = f2tf32(v.z);
            dst[((n0 + 3) * 4 + ls) * 2 + reg] = f2tf32(v.w);
        }
        __syncthreads();

        // ---- mainloop over 4 k8-steps ----
#pragma unroll
        for (int ki = 0; ki < 4; ki++) {
            unsigned a[2][4], b[4][2];
#pragma unroll
            for (int m = 0; m < 2; m++) {
                int mi = warpM * 2 + m;
                uint4 af = *(const uint4*)&AsF[(((ki << 3) + mi) << 7) + lane * 4];
                a[m][0] = af.x; a[m][1] = af.y; a[m][2] = af.z; a[m][3] = af.w;
            }
#pragma unroll
            for (int n = 0; n < 4; n++) {
                int ni = warpN * 4 + n;
                uint2 bf = *(const uint2*)&BsF[(((ki << 3) + ni) << 6) + lane * 2];
                b[n][0] = bf.x; b[n][1] = bf.y;
            }
#pragma unroll
            for (int m = 0; m < 2; m++)
#pragma unroll
                for (int n = 0; n < 4; n++) {
                    asm volatile(
                        "mma.sync.aligned.m16n8k8.row.col.f32.tf32.tf32.f32 "
                        "{%0,%1,%2,%3}, {%4,%5,%6,%7}, {%8,%9}, {%0,%1,%2,%3};"
                        : "+f"(acc[m][n][0]), "+f"(acc[m][n][1]),
                          "+f"(acc[m][n][2]), "+f"(acc[m][n][3])
                        : "r"(a[m][0]), "r"(a[m][1]), "r"(a[m][2]), "r"(a[m][3]),
                          "r"(b[n][0]), "r"(b[n][1]));
                }
        }
        __syncthreads();
    }

    // ---- epilogue: bias + relu, float2 stores ----
    int gr = lane >> 2;            // 0..7
    int gc = (lane & 3) * 2;       // 0,2,4,6
#pragma unroll
    for (int m = 0; m < 2; m++) {
        int row0 = rowBase + (warpM * 2 + m) * 16 + gr;
#pragma unroll
        for (int n = 0; n < 4; n++) {
            int col = colBase + (warpN * 4 + n) * 8 + gc;
            float b0 = bias[col], b1 = bias[col + 1];
            float2 v0, v1;
            v0.x = acc[m][n][0] + b0; v0.y = acc[m][n][1] + b1;
            v1.x = acc[m][n][2] + b0; v1.y = acc[m][n][3] + b1;
            v0.x = v0.x > 0.f ? v0.x : 0.f;
            v0.y = v0.y > 0.f ? v0.y : 0.f;
            v1.x = v1.x > 0.f ? v1.x : 0.f;
            v1.y = v1.y > 0.f ? v1.y : 0.f;
            *(float2*)&C[(size_t)row0 * N + col] = v0;
            *(float2*)&C[(size_t)(row0 + 8) * N + col] = v1;
        }
    }
}

// ---------------- pooling + MLP head ----------------------------------------
__global__ void k_pool(const float* __restrict__ x3, float* __restrict__ h) {
    int g = blockIdx.x;
    int f = threadIdx.x;
    const float* base = x3 + (size_t)g * PTS * 512 + f;
    float s = 0.f, m = -INFINITY;
#pragma unroll 8
    for (int n = 0; n < PTS; n++) {
        float v = base[(size_t)n * 512];
        s += v;
        m = fmaxf(m, v);
    }
    h[g * 1024 + f] = s * (1.0f / PTS);
    h[g * 1024 + 512 + f] = m;
}

__global__ void k_mlp1(const float* __restrict__ h, const float* __restrict__ W,
                       const float* __restrict__ b, float* __restrict__ h2) {
    __shared__ float hs[1024];
    int g = blockIdx.x;
    int c = threadIdx.x;
    for (int k = c; k < 1024; k += 512) hs[k] = h[g * 1024 + k];
    __syncthreads();
    float acc = b[c];
#pragma unroll 4
    for (int k = 0; k < 1024; k++) acc += hs[k] * W[k * 512 + c];
    h2[g * 512 + c] = acc > 0.f ? acc : 0.f;
}

__global__ void k_mlp2(const float* __restrict__ h2, const float* __restrict__ W,
                       const float* __restrict__ b, float* __restrict__ out) {
    int idx = blockIdx.x * blockDim.x + threadIdx.x;
    if (idx >= N_GRAPHS * 10) return;
    int g = idx / 10;
    int c = idx % 10;
    float acc = b[c];
    const float* hr = h2 + g * 512;
#pragma unroll 8
    for (int k = 0; k < 512; k++) acc += hr[k] * W[k * 10 + c];
    out[idx] = acc;
}

// ---------------- host orchestration ----------------------------------------
extern "C" void kernel_launch(void* const* d_in, const int* in_sizes, int n_in,
                              void* d_out, int out_size) {
    const float* x   = (const float*)d_in[0];
    const int*   ei  = (const int*)d_in[1];   // int32 (JAX x64-disabled)
    const float* W1  = (const float*)d_in[3];
    const float* b1  = (const float*)d_in[4];
    const float* W2  = (const float*)d_in[5];
    const float* b2  = (const float*)d_in[6];
    const float* W3  = (const float*)d_in[7];
    const float* b3  = (const float*)d_in[8];
    const float* Wm1 = (const float*)d_in[9];
    const float* bm1 = (const float*)d_in[10];
    const float* Wm2 = (const float*)d_in[11];
    const float* bm2 = (const float*)d_in[12];
    float* out = (float*)d_out;

    float *bufA, *bufB, *bufC, *dinv, *ccoef, *h, *h2;
    int *cnt, *cursor, *tmp, *bsum, *boff, *rowptr, *csrc;
    cudaGetSymbolAddress((void**)&bufA,   g_bufA);
    cudaGetSymbolAddress((void**)&bufB,   g_bufB);
    cudaGetSymbolAddress((void**)&bufC,   g_bufC);
    cudaGetSymbolAddress((void**)&dinv,   g_dinv);
    cudaGetSymbolAddress((void**)&cnt,    g_cnt);
    cudaGetSymbolAddress((void**)&cursor, g_cursor);
    cudaGetSymbolAddress((void**)&tmp,    g_tmp);
    cudaGetSymbolAddress((void**)&bsum,   g_bsum);
    cudaGetSymbolAddress((void**)&boff,   g_boff);
    cudaGetSymbolAddress((void**)&rowptr, g_rowptr);
    cudaGetSymbolAddress((void**)&csrc,   g_csrc);
    cudaGetSymbolAddress((void**)&ccoef,  g_ccoef);
    cudaGetSymbolAddress((void**)&h,      g_h);
    cudaGetSymbolAddress((void**)&h2,     g_h2);

    // ---- CSR build (by destination) + normalization ----
    k_zero2<<<N_NODES / 256, 256>>>(cnt, cursor);
    k_count<<<N_EDGES / 256, 256>>>(ei, cnt);
    k_dinv<<<N_NODES / 256, 256>>>(cnt, dinv);
    k_scan1<<<64, 1024>>>(cnt, tmp, bsum);
    k_scan2<<<1, 64>>>(bsum, boff);
    k_scan3<<<N_NODES / 256, 256>>>(tmp, boff, rowptr);
    k_fill<<<N_EDGES / 256, 256>>>(ei, dinv, rowptr, cursor, csrc, ccoef);

    // ---- layer 1: aggregate F=3 (y0 -> bufB), GEMM 3->64 (x1 -> bufA) ----
    k_agg3<<<N_NODES / 256, 256>>>(rowptr, csrc, ccoef, x, dinv, bufB);
    k_gemm1<<<(N_NODES * 64) / 256, 256>>>(bufB, W1, b1, bufA);

    // ---- layer 2: aggregate F=64 (bufA -> bufC), tf32 GEMM 64->256 (-> bufA) ----
    k_agg64<<<(N_NODES * 32) / 256, 256>>>(rowptr, csrc, ccoef, bufA, dinv, bufC);
    {
        dim3 grid(256 / 64, N_NODES / 128);
        k_tf32gemm<<<grid, 256>>>(bufC, W2, b2, bufA, 256, 64);
    }

    // ---- layer 3: aggregate F=256 (bufA -> bufB), tf32 GEMM 256->512 (-> bufC) ----
    k_agg256<<<(N_NODES * 32) / 256, 256>>>(rowptr, csrc, ccoef, bufA, dinv, bufB);
    {
        dim3 grid(512 / 64, N_NODES / 128);
        k_tf32gemm<<<grid, 256>>>(bufB, W3, b3, bufC, 512, 256);
    }

    // ---- pooling + MLP head ----
    k_pool<<<N_GRAPHS, 512>>>(bufC, h);
    k_mlp1<<<N_GRAPHS, 512>>>(h, Wm1, bm1, h2);
    k_mlp2<<<(N_GRAPHS * 10 + 255) / 256, 256>>>(h2, Wm2, bm2, out);

    (void)in_sizes; (void)n_in; (void)out_size;
}

// round 15
// speedup vs baseline: 1.3644x; 1.3644x over previous
#include <cuda_runtime.h>
#include <math.h>

#define N_NODES 65536
#define N_EDGES 524288
#define N_GRAPHS 64
#define PTS 1024
#define FMAX 512

// ---------------- scratch (device globals: no allocation allowed) ----------
__device__ float g_bufA[(size_t)N_NODES * FMAX];
__device__ float g_bufB[(size_t)N_NODES * FMAX];
__device__ float g_bufC[(size_t)N_NODES * FMAX];
__device__ float g_dinv[N_NODES];
__device__ int   g_cnt[N_NODES];
__device__ int   g_cursor[N_NODES];
__device__ int   g_tmp[N_NODES];
__device__ int   g_bsum[64];
__device__ int   g_boff[64];
__device__ int   g_rowptr[N_NODES + 1];
__device__ int   g_csrc[N_EDGES];
__device__ float g_ccoef[N_EDGES];
__device__ float g_h[N_GRAPHS * 1024];
__device__ float g_h2[N_GRAPHS * 512];

// ---------------- counters / normalization ---------------------------------
__global__ void k_zero2(int* cnt, int* cursor) {
    int i = blockIdx.x * blockDim.x + threadIdx.x;
    if (i < N_NODES) { cnt[i] = 0; cursor[i] = 0; }
}

__global__ void k_count(const int* __restrict__ ei, int* __restrict__ cnt) {
    int e = blockIdx.x * blockDim.x + threadIdx.x;
    if (e < N_EDGES) atomicAdd(&cnt[ei[N_EDGES + e]], 1);
}

__global__ void k_dinv(const int* __restrict__ cnt, float* __restrict__ dinv) {
    int i = blockIdx.x * blockDim.x + threadIdx.x;
    if (i < N_NODES) dinv[i] = rsqrtf((float)(cnt[i] + 1));   // +1 self-loop
}

// ---------------- exclusive scan of cnt -> rowptr ---------------------------
__global__ void k_scan1(const int* __restrict__ cnt, int* __restrict__ tmp,
                        int* __restrict__ bsum) {
    __shared__ int s[1024];
    int t = threadIdx.x;
    int i = blockIdx.x * 1024 + t;
    s[t] = cnt[i];
    __syncthreads();
    for (int off = 1; off < 1024; off <<= 1) {
        int x = (t >= off) ? s[t - off] : 0;
        __syncthreads();
        s[t] += x;
        __syncthreads();
    }
    tmp[i] = s[t];
    if (t == 1023) bsum[blockIdx.x] = s[t];
}

__global__ void k_scan2(const int* __restrict__ bsum, int* __restrict__ boff) {
    __shared__ int s[64];
    int t = threadIdx.x;
    s[t] = bsum[t];
    __syncthreads();
    for (int off = 1; off < 64; off <<= 1) {
        int x = (t >= off) ? s[t - off] : 0;
        __syncthreads();
        s[t] += x;
        __syncthreads();
    }
    boff[t] = (t == 0) ? 0 : s[t - 1];
}

__global__ void k_scan3(const int* __restrict__ tmp, const int* __restrict__ boff,
                        int* __restrict__ rowptr) {
    int i = blockIdx.x * blockDim.x + threadIdx.x;
    if (i < N_NODES) {
        rowptr[i + 1] = tmp[i] + boff[i >> 10];
        if (i == 0) rowptr[0] = 0;
    }
}

__global__ void k_fill(const int* __restrict__ ei, const float* __restrict__ dinv,
                       const int* __restrict__ rowptr, int* __restrict__ cursor,
                       int* __restrict__ csrc, float* __restrict__ ccoef) {
    int e = blockIdx.x * blockDim.x + threadIdx.x;
    if (e >= N_EDGES) return;
    int r = ei[e];
    int c = ei[N_EDGES + e];
    int slot = rowptr[c] + atomicAdd(&cursor[c], 1);
    csrc[slot] = r;
    ccoef[slot] = dinv[r] * dinv[c];
}

// ---------------- CSR aggregations ------------------------------------------
__global__ void k_agg3(const int* __restrict__ rowptr, const int* __restrict__ csrc,
                       const float* __restrict__ ccoef, const float* __restrict__ x,
                       const float* __restrict__ dinv, float* __restrict__ y) {
    int i = blockIdx.x * blockDim.x + threadIdx.x;
    if (i >= N_NODES) return;
    float d = dinv[i];
    float d2 = d * d;
    float a0 = x[i * 3 + 0] * d2, a1 = x[i * 3 + 1] * d2, a2 = x[i * 3 + 2] * d2;
    int beg = rowptr[i], end = rowptr[i + 1];
    for (int j = beg; j < end; j++) {
        int s = csrc[j];
        float w = ccoef[j];
        a0 += x[s * 3 + 0] * w;
        a1 += x[s * 3 + 1] * w;
        a2 += x[s * 3 + 2] * w;
    }
    y[i * 3 + 0] = a0;
    y[i * 3 + 1] = a1;
    y[i * 3 + 2] = a2;
}

__global__ void k_agg64(const int* __restrict__ rowptr, const int* __restrict__ csrc,
                        const float* __restrict__ ccoef, const float* __restrict__ xw,
                        const float* __restrict__ dinv, float* __restrict__ out) {
    int w = (blockIdx.x * blockDim.x + threadIdx.x) >> 5;
    int lane = threadIdx.x & 31;
    if (w >= N_NODES) return;
    float d = dinv[w];
    float d2 = d * d;
    float2 a = ((const float2*)&xw[(size_t)w * 64])[lane];
    a.x *= d2; a.y *= d2;
    int beg = rowptr[w], end = rowptr[w + 1];
    for (int j = beg; j < end; j++) {
        int s = csrc[j];
        float c = ccoef[j];
        float2 v = ((const float2*)&xw[(size_t)s * 64])[lane];
        a.x += v.x * c;
        a.y += v.y * c;
    }
    ((float2*)&out[(size_t)w * 64])[lane] = a;
}

__global__ void k_agg256(const int* __restrict__ rowptr, const int* __restrict__ csrc,
                         const float* __restrict__ ccoef, const float* __restrict__ xw,
                         const float* __restrict__ dinv, float* __restrict__ out) {
    int w = (blockIdx.x * blockDim.x + threadIdx.x) >> 5;
    int lane = threadIdx.x & 31;
    if (w >= N_NODES) return;
    float d = dinv[w];
    float d2 = d * d;
    const float4* selfrow = (const float4*)&xw[(size_t)w * 256];
    float4 a0 = selfrow[lane];
    float4 a1 = selfrow[lane + 32];
    a0.x *= d2; a0.y *= d2; a0.z *= d2; a0.w *= d2;
    a1.x *= d2; a1.y *= d2; a1.z *= d2; a1.w *= d2;
    int beg = rowptr[w], end = rowptr[w + 1];
    for (int j = beg; j < end; j++) {
        int s = csrc[j];
        float c = ccoef[j];
        const float4* row = (const float4*)&xw[(size_t)s * 256];
        float4 v0 = row[lane];
        float4 v1 = row[lane + 32];
        a0.x += v0.x * c; a0.y += v0.y * c; a0.z += v0.z * c; a0.w += v0.w * c;
        a1.x += v1.x * c; a1.y += v1.y * c; a1.z += v1.z * c; a1.w += v1.w * c;
    }
    float4* o = (float4*)&out[(size_t)w * 256];
    o[lane] = a0;
    o[lane + 32] = a1;
}

// ---------------- layer-1 GEMM (K=3, N=64) ----------------------------------
__global__ void k_gemm1(const float* __restrict__ y0, const float* __restrict__ W,
                        const float* __restrict__ bias, float* __restrict__ x1) {
    __shared__ float Ws[192];
    __shared__ float bs[64];
    int t = threadIdx.x;
    if (t < 192) Ws[t] = W[t];
    if (t < 64) bs[t] = bias[t];
    __syncthreads();
    int idx = blockIdx.x * blockDim.x + t;
    int i = idx >> 6;
    int j = idx & 63;
    float a0 = y0[i * 3 + 0], a1 = y0[i * 3 + 1], a2 = y0[i * 3 + 2];
    float v = a0 * Ws[j] + a1 * Ws[64 + j] + a2 * Ws[128 + j] + bs[j];
    x1[idx] = v > 0.f ? v : 0.f;
}

// ---------------- tf32 tensor-core GEMM v2 ----------------------------------
// Block 128x64, BK=16, 8 warps (32x32 warp tile), mma.sync m16n8k8 tf32.
// Row-major smem with bank-exact padded strides; cp.async double buffering.
#define ASTRIDE 20   // gr*20 mod 32 covers {0,4,..28}; +tg -> all 32 banks
#define BSTRIDE 72   // 72 mod 32 = 8; tg*8+gr -> all 32 banks

__device__ __forceinline__ unsigned f2tf32(float x) {
    unsigned r;
    asm("cvt.rna.tf32.f32 %0, %1;" : "=r"(r) : "f"(x));
    return r;
}

__device__ __forceinline__ void cp_async16(void* smem_dst, const void* gmem_src) {
    unsigned sa = (unsigned)__cvta_generic_to_shared(smem_dst);
    asm volatile("cp.async.cg.shared.global [%0], [%1], 16;\n"
                 :: "r"(sa), "l"(gmem_src) : "memory");
}

__device__ __forceinline__ void cp_commit() {
    asm volatile("cp.async.commit_group;\n" ::: "memory");
}

template <int NW>
__device__ __forceinline__ void cp_wait() {
    asm volatile("cp.async.wait_group %0;\n" :: "n"(NW) : "memory");
}

__global__ __launch_bounds__(256)
void k_tf32gemm(const float* __restrict__ A, const float* __restrict__ Bm,
                const float* __restrict__ bias, float* __restrict__ C,
                int N, int K) {
    __shared__ __align__(16) float As[2][128 * ASTRIDE];   // 20 KB
    __shared__ __align__(16) float Bs[2][16 * BSTRIDE];    //  9 KB

    int tid = threadIdx.x;
    int lane = tid & 31;
    int warp = tid >> 5;
    int warpM = warp >> 1;        // 0..3
    int warpN = warp & 1;         // 0..1
    int rowBase = blockIdx.y * 128;
    int colBase = blockIdx.x * 64;

    // staging coords (per thread)
    int sArow = tid >> 2;                 // 0..63 (+64 for 2nd chunk)
    int sAk4  = (tid & 3) * 4;            // 0,4,8,12
    int sBrow = tid >> 4;                 // 0..15
    int sBn4  = (tid & 15) * 4;           // 0..60

    float acc[2][4][4];
#pragma unroll
    for (int m = 0; m < 2; m++)
#pragma unroll
        for (int n = 0; n < 4; n++)
#pragma unroll
            for (int q = 0; q < 4; q++) acc[m][n][q] = 0.f;

    int nt = K >> 4;   // number of BK=16 tiles

    // prologue: stage tile 0 into buffer 0
    {
        const float* ga0 = &A[(size_t)(rowBase + sArow) * K + sAk4];
        const float* ga1 = &A[(size_t)(rowBase + sArow + 64) * K + sAk4];
        cp_async16(&As[0][sArow * ASTRIDE + sAk4], ga0);
        cp_async16(&As[0][(sArow + 64) * ASTRIDE + sAk4], ga1);
        const float* gb = &Bm[(size_t)sBrow * N + colBase + sBn4];
        cp_async16(&Bs[0][sBrow * BSTRIDE + sBn4], gb);
        cp_commit();
    }

    // fragment-load coords
    int gr = lane >> 2;      // 0..7
    int tg = lane & 3;       // 0..3

    for (int t = 0; t < nt; t++) {
        int cur = t & 1;
        if (t + 1 < nt) {
            int nxt = cur ^ 1;
            int k0 = (t + 1) << 4;
            const float* ga0 = &A[(size_t)(rowBase + sArow) * K + k0 + sAk4];
            const float* ga1 = &A[(size_t)(rowBase + sArow + 64) * K + k0 + sAk4];
            cp_async16(&As[nxt][sArow * ASTRIDE + sAk4], ga0);
            cp_async16(&As[nxt][(sArow + 64) * ASTRIDE + sAk4], ga1);
            const float* gb = &Bm[(size_t)(k0 + sBrow) * N + colBase + sBn4];
            cp_async16(&Bs[nxt][sBrow * BSTRIDE + sBn4], gb);
            cp_commit();
            cp_wait<1>();
        } else {
            cp_wait<0>();
        }
        __syncthreads();

#pragma unroll
        for (int ki = 0; ki < 2; ki++) {
            unsigned a[2][4];
#pragma unroll
            for (int m = 0; m < 2; m++) {
                const float* base =
                    &As[cur][((warpM * 2 + m) * 16 + gr) * ASTRIDE + ki * 8 + tg];
                a[m][0] = f2tf32(base[0]);
                a[m][1] = f2tf32(base[8 * ASTRIDE]);
                a[m][2] = f2tf32(base[4]);
                a[m][3] = f2tf32(base[8 * ASTRIDE + 4]);
            }
            unsigned b[4][2];
#pragma unroll
            for (int n = 0; n < 4; n++) {
                const float* bp =
                    &Bs[cur][(ki * 8 + tg) * BSTRIDE + (warpN * 4 + n) * 8 + gr];
                b[n][0] = f2tf32(bp[0]);
                b[n][1] = f2tf32(bp[4 * BSTRIDE]);
            }
#pragma unroll
            for (int m = 0; m < 2; m++)
#pragma unroll
                for (int n = 0; n < 4; n++) {
                    asm volatile(
                        "mma.sync.aligned.m16n8k8.row.col.f32.tf32.tf32.f32 "
                        "{%0,%1,%2,%3}, {%4,%5,%6,%7}, {%8,%9}, {%0,%1,%2,%3};"
                        : "+f"(acc[m][n][0]), "+f"(acc[m][n][1]),
                          "+f"(acc[m][n][2]), "+f"(acc[m][n][3])
                        : "r"(a[m][0]), "r"(a[m][1]), "r"(a[m][2]), "r"(a[m][3]),
                          "r"(b[n][0]), "r"(b[n][1]));
                }
        }
        __syncthreads();
    }

    // ---- epilogue: bias + relu, float2 stores (validated layout) ----
    int gc = tg * 2;
#pragma unroll
    for (int m = 0; m < 2; m++) {
        int row0 = rowBase + (warpM * 2 + m) * 16 + gr;
#pragma unroll
        for (int n = 0; n < 4; n++) {
            int col = colBase + (warpN * 4 + n) * 8 + gc;
            float b0 = bias[col], b1 = bias[col + 1];
            float2 v0, v1;
            v0.x = acc[m][n][0] + b0; v0.y = acc[m][n][1] + b1;
            v1.x = acc[m][n][2] + b0; v1.y = acc[m][n][3] + b1;
            v0.x = v0.x > 0.f ? v0.x : 0.f;
            v0.y = v0.y > 0.f ? v0.y : 0.f;
            v1.x = v1.x > 0.f ? v1.x : 0.f;
            v1.y = v1.y > 0.f ? v1.y : 0.f;
            *(float2*)&C[(size_t)row0 * N + col] = v0;
            *(float2*)&C[(size_t)(row0 + 8) * N + col] = v1;
        }
    }
}

// ---------------- pooling + MLP head ----------------------------------------
__global__ void k_pool(const float* __restrict__ x3, float* __restrict__ h) {
    int g = blockIdx.x;
    int f = threadIdx.x;
    const float* base = x3 + (size_t)g * PTS * 512 + f;
    float s = 0.f, m = -INFINITY;
#pragma unroll 8
    for (int n = 0; n < PTS; n++) {
        float v = base[(size_t)n * 512];
        s += v;
        m = fmaxf(m, v);
    }
    h[g * 1024 + f] = s * (1.0f / PTS);
    h[g * 1024 + 512 + f] = m;
}

__global__ void k_mlp1(const float* __restrict__ h, const float* __restrict__ W,
                       const float* __restrict__ b, float* __restrict__ h2) {
    __shared__ float hs[1024];
    int g = blockIdx.x;
    int c = threadIdx.x;
    for (int k = c; k < 1024; k += 512) hs[k] = h[g * 1024 + k];
    __syncthreads();
    float acc = b[c];
#pragma unroll 4
    for (int k = 0; k < 1024; k++) acc += hs[k] * W[k * 512 + c];
    h2[g * 512 + c] = acc > 0.f ? acc : 0.f;
}

__global__ void k_mlp2(const float* __restrict__ h2, const float* __restrict__ W,
                       const float* __restrict__ b, float* __restrict__ out) {
    int idx = blockIdx.x * blockDim.x + threadIdx.x;
    if (idx >= N_GRAPHS * 10) return;
    int g = idx / 10;
    int c = idx % 10;
    float acc = b[c];
    const float* hr = h2 + g * 512;
#pragma unroll 8
    for (int k = 0; k < 512; k++) acc += hr[k] * W[k * 10 + c];
    out[idx] = acc;
}

// ---------------- host orchestration ----------------------------------------
extern "C" void kernel_launch(void* const* d_in, const int* in_sizes, int n_in,
                              void* d_out, int out_size) {
    const float* x   = (const float*)d_in[0];
    const int*   ei  = (const int*)d_in[1];   // int32 (JAX x64-disabled)
    const float* W1  = (const float*)d_in[3];
    const float* b1  = (const float*)d_in[4];
    const float* W2  = (const float*)d_in[5];
    const float* b2  = (const float*)d_in[6];
    const float* W3  = (const float*)d_in[7];
    const float* b3  = (const float*)d_in[8];
    const float* Wm1 = (const float*)d_in[9];
    const float* bm1 = (const float*)d_in[10];
    const float* Wm2 = (const float*)d_in[11];
    const float* bm2 = (const float*)d_in[12];
    float* out = (float*)d_out;

    float *bufA, *bufB, *bufC, *dinv, *ccoef, *h, *h2;
    int *cnt, *cursor, *tmp, *bsum, *boff, *rowptr, *csrc;
    cudaGetSymbolAddress((void**)&bufA,   g_bufA);
    cudaGetSymbolAddress((void**)&bufB,   g_bufB);
    cudaGetSymbolAddress((void**)&bufC,   g_bufC);
    cudaGetSymbolAddress((void**)&dinv,   g_dinv);
    cudaGetSymbolAddress((void**)&cnt,    g_cnt);
    cudaGetSymbolAddress((void**)&cursor, g_cursor);
    cudaGetSymbolAddress((void**)&tmp,    g_tmp);
    cudaGetSymbolAddress((void**)&bsum,   g_bsum);
    cudaGetSymbolAddress((void**)&boff,   g_boff);
    cudaGetSymbolAddress((void**)&rowptr, g_rowptr);
    cudaGetSymbolAddress((void**)&csrc,   g_csrc);
    cudaGetSymbolAddress((void**)&ccoef,  g_ccoef);
    cudaGetSymbolAddress((void**)&h,      g_h);
    cudaGetSymbolAddress((void**)&h2,     g_h2);

    // ---- CSR build + normalization. Launch index 3 (the one ncu captures)
    // is a small-grid DIAGNOSTIC clone of the new tf32 GEMM on scratch data:
    // its profile (tensor% vs fma%) decides staging-fix vs mma-emulation.
    // Reads stale-but-deterministic bufB; writes bufA rows<8192, fully
    // overwritten by gemm1/gemm2 before any consumer reads. ----
    k_zero2<<<N_NODES / 256, 256>>>(cnt, cursor);                 // 0
    k_count<<<N_EDGES / 256, 256>>>(ei, cnt);                     // 1
    k_dinv<<<N_NODES / 256, 256>>>(cnt, dinv);                    // 2
    {
        dim3 gprof(512 / 64, 64);
        k_tf32gemm<<<gprof, 256>>>(bufB, W3, b3, bufA, 512, 256); // 3 (profiled)
    }
    k_scan1<<<64, 1024>>>(cnt, tmp, bsum);                        // 4
    k_scan2<<<1, 64>>>(bsum, boff);                               // 5
    k_scan3<<<N_NODES / 256, 256>>>(tmp, boff, rowptr);           // 6
    k_fill<<<N_EDGES / 256, 256>>>(ei, dinv, rowptr, cursor, csrc, ccoef); // 7

    // ---- layer 1: aggregate F=3 (y0 -> bufB), GEMM 3->64 (x1 -> bufA) ----
    k_agg3<<<N_NODES / 256, 256>>>(rowptr, csrc, ccoef, x, dinv, bufB);
    k_gemm1<<<(N_NODES * 64) / 256, 256>>>(bufB, W1, b1, bufA);

    // ---- layer 2: aggregate F=64 (bufA -> bufC), tf32 GEMM 64->256 (-> bufA) ----
    k_agg64<<<(N_NODES * 32) / 256, 256>>>(rowptr, csrc, ccoef, bufA, dinv, bufC);
    {
        dim3 grid(256 / 64, N_NODES / 128);
        k_tf32gemm<<<grid, 256>>>(bufC, W2, b2, bufA, 256, 64);
    }

    // ---- layer 3: aggregate F=256 (bufA -> bufB), tf32 GEMM 256->512 (-> bufC) ----
    k_agg256<<<(N_NODES * 32) / 256, 256>>>(rowptr, csrc, ccoef, bufA, dinv, bufB);
    {
        dim3 grid(512 / 64, N_NODES / 128);
        k_tf32gemm<<<grid, 256>>>(bufB, W3, b3, bufC, 512, 256);
    }

    // ---- pooling + MLP head ----
    k_pool<<<N_GRAPHS, 512>>>(bufC, h);
    k_mlp1<<<N_GRAPHS, 512>>>(h, Wm1, bm1, h2);
    k_mlp2<<<(N_GRAPHS * 10 + 255) / 256, 256>>>(h2, Wm2, bm2, out);

    (void)in_sizes; (void)n_in; (void)out_size;
}

// round 16
// speedup vs baseline: 1.4072x; 1.0314x over previous
#include <cuda_runtime.h>
#include <math.h>

#define N_NODES 65536
#define N_EDGES 524288
#define N_GRAPHS 64
#define PTS 1024
#define FMAX 512

// ---------------- scratch (device globals: no allocation allowed) ----------
__device__ float g_bufA[(size_t)N_NODES * FMAX];
__device__ float g_bufB[(size_t)N_NODES * FMAX];
__device__ float g_bufC[(size_t)N_NODES * FMAX];
__device__ float g_dinv[N_NODES];
__device__ int   g_cnt[N_NODES];
__device__ int   g_cursor[N_NODES];
__device__ int   g_tmp[N_NODES];
__device__ int   g_bsum[64];
__device__ int   g_boff[64];
__device__ int   g_rowptr[N_NODES + 1];
__device__ int   g_csrc[N_EDGES];
__device__ float g_ccoef[N_EDGES];
__device__ float g_w2r[64 * 256];      // tf32-pre-rounded W2
__device__ float g_w3r[256 * 512];     // tf32-pre-rounded W3
__device__ float g_h[N_GRAPHS * 1024];
__device__ float g_h2[N_GRAPHS * 512];

// ---------------- tf32 rounding helper --------------------------------------
__device__ __forceinline__ float roundtf32(float x) {
    unsigned u;
    asm("cvt.rna.tf32.f32 %0, %1;" : "=r"(u) : "f"(x));
    return __uint_as_float(u);
}

// ---------------- counters / normalization ---------------------------------
__global__ void k_zero2(int* cnt, int* cursor) {
    int i = blockIdx.x * blockDim.x + threadIdx.x;
    if (i < N_NODES) { cnt[i] = 0; cursor[i] = 0; }
}

__global__ void k_count(const int* __restrict__ ei, int* __restrict__ cnt) {
    int e = blockIdx.x * blockDim.x + threadIdx.x;
    if (e < N_EDGES) atomicAdd(&cnt[ei[N_EDGES + e]], 1);
}

__global__ void k_dinv(const int* __restrict__ cnt, float* __restrict__ dinv) {
    int i = blockIdx.x * blockDim.x + threadIdx.x;
    if (i < N_NODES) dinv[i] = rsqrtf((float)(cnt[i] + 1));   // +1 self-loop
}

// ---------------- pre-round weights to tf32 ---------------------------------
__global__ void k_round(const float* __restrict__ src, float* __restrict__ dst,
                        int n) {
    int i = blockIdx.x * blockDim.x + threadIdx.x;
    if (i < n) dst[i] = roundtf32(src[i]);
}

// ---------------- exclusive scan of cnt -> rowptr ---------------------------
__global__ void k_scan1(const int* __restrict__ cnt, int* __restrict__ tmp,
                        int* __restrict__ bsum) {
    __shared__ int s[1024];
    int t = threadIdx.x;
    int i = blockIdx.x * 1024 + t;
    s[t] = cnt[i];
    __syncthreads();
    for (int off = 1; off < 1024; off <<= 1) {
        int x = (t >= off) ? s[t - off] : 0;
        __syncthreads();
        s[t] += x;
        __syncthreads();
    }
    tmp[i] = s[t];
    if (t == 1023) bsum[blockIdx.x] = s[t];
}

__global__ void k_scan2(const int* __restrict__ bsum, int* __restrict__ boff) {
    __shared__ int s[64];
    int t = threadIdx.x;
    s[t] = bsum[t];
    __syncthreads();
    for (int off = 1; off < 64; off <<= 1) {
        int x = (t >= off) ? s[t - off] : 0;
        __syncthreads();
        s[t] += x;
        __syncthreads();
    }
    boff[t] = (t == 0) ? 0 : s[t - 1];
}

__global__ void k_scan3(const int* __restrict__ tmp, const int* __restrict__ boff,
                        int* __restrict__ rowptr) {
    int i = blockIdx.x * blockDim.x + threadIdx.x;
    if (i < N_NODES) {
        rowptr[i + 1] = tmp[i] + boff[i >> 10];
        if (i == 0) rowptr[0] = 0;
    }
}

__global__ void k_fill(const int* __restrict__ ei, const float* __restrict__ dinv,
                       const int* __restrict__ rowptr, int* __restrict__ cursor,
                       int* __restrict__ csrc, float* __restrict__ ccoef) {
    int e = blockIdx.x * blockDim.x + threadIdx.x;
    if (e >= N_EDGES) return;
    int r = ei[e];
    int c = ei[N_EDGES + e];
    int slot = rowptr[c] + atomicAdd(&cursor[c], 1);
    csrc[slot] = r;
    ccoef[slot] = dinv[r] * dinv[c];
}

// ---------------- CSR aggregations ------------------------------------------
__global__ void k_agg3(const int* __restrict__ rowptr, const int* __restrict__ csrc,
                       const float* __restrict__ ccoef, const float* __restrict__ x,
                       const float* __restrict__ dinv, float* __restrict__ y) {
    int i = blockIdx.x * blockDim.x + threadIdx.x;
    if (i >= N_NODES) return;
    float d = dinv[i];
    float d2 = d * d;
    float a0 = x[i * 3 + 0] * d2, a1 = x[i * 3 + 1] * d2, a2 = x[i * 3 + 2] * d2;
    int beg = rowptr[i], end = rowptr[i + 1];
    for (int j = beg; j < end; j++) {
        int s = csrc[j];
        float w = ccoef[j];
        a0 += x[s * 3 + 0] * w;
        a1 += x[s * 3 + 1] * w;
        a2 += x[s * 3 + 2] * w;
    }
    y[i * 3 + 0] = a0;
    y[i * 3 + 1] = a1;
    y[i * 3 + 2] = a2;
}

// Output rounded to tf32 (consumed raw by the tensor-core GEMM)
__global__ void k_agg64(const int* __restrict__ rowptr, const int* __restrict__ csrc,
                        const float* __restrict__ ccoef, const float* __restrict__ xw,
                        const float* __restrict__ dinv, float* __restrict__ out) {
    int w = (blockIdx.x * blockDim.x + threadIdx.x) >> 5;
    int lane = threadIdx.x & 31;
    if (w >= N_NODES) return;
    float d = dinv[w];
    float d2 = d * d;
    float2 a = ((const float2*)&xw[(size_t)w * 64])[lane];
    a.x *= d2; a.y *= d2;
    int beg = rowptr[w], end = rowptr[w + 1];
    for (int j = beg; j < end; j++) {
        int s = csrc[j];
        float c = ccoef[j];
        float2 v = ((const float2*)&xw[(size_t)s * 64])[lane];
        a.x += v.x * c;
        a.y += v.y * c;
    }
    a.x = roundtf32(a.x);
    a.y = roundtf32(a.y);
    ((float2*)&out[(size_t)w * 64])[lane] = a;
}

__global__ void k_agg256(const int* __restrict__ rowptr, const int* __restrict__ csrc,
                         const float* __restrict__ ccoef, const float* __restrict__ xw,
                         const float* __restrict__ dinv, float* __restrict__ out) {
    int w = (blockIdx.x * blockDim.x + threadIdx.x) >> 5;
    int lane = threadIdx.x & 31;
    if (w >= N_NODES) return;
    float d = dinv[w];
    float d2 = d * d;
    const float4* selfrow = (const float4*)&xw[(size_t)w * 256];
    float4 a0 = selfrow[lane];
    float4 a1 = selfrow[lane + 32];
    a0.x *= d2; a0.y *= d2; a0.z *= d2; a0.w *= d2;
    a1.x *= d2; a1.y *= d2; a1.z *= d2; a1.w *= d2;
    int beg = rowptr[w], end = rowptr[w + 1];
    for (int j = beg; j < end; j++) {
        int s = csrc[j];
        float c = ccoef[j];
        const float4* row = (const float4*)&xw[(size_t)s * 256];
        float4 v0 = row[lane];
        float4 v1 = row[lane + 32];
        a0.x += v0.x * c; a0.y += v0.y * c; a0.z += v0.z * c; a0.w += v0.w * c;
        a1.x += v1.x * c; a1.y += v1.y * c; a1.z += v1.z * c; a1.w += v1.w * c;
    }
    a0.x = roundtf32(a0.x); a0.y = roundtf32(a0.y);
    a0.z = roundtf32(a0.z); a0.w = roundtf32(a0.w);
    a1.x = roundtf32(a1.x); a1.y = roundtf32(a1.y);
    a1.z = roundtf32(a1.z); a1.w = roundtf32(a1.w);
    float4* o = (float4*)&out[(size_t)w * 256];
    o[lane] = a0;
    o[lane + 32] = a1;
}

// ---------------- layer-1 GEMM (K=3, N=64) ----------------------------------
__global__ void k_gemm1(const float* __restrict__ y0, const float* __restrict__ W,
                        const float* __restrict__ bias, float* __restrict__ x1) {
    __shared__ float Ws[192];
    __shared__ float bs[64];
    int t = threadIdx.x;
    if (t < 192) Ws[t] = W[t];
    if (t < 64) bs[t] = bias[t];
    __syncthreads();
    int idx = blockIdx.x * blockDim.x + t;
    int i = idx >> 6;
    int j = idx & 63;
    float a0 = y0[i * 3 + 0], a1 = y0[i * 3 + 1], a2 = y0[i * 3 + 2];
    float v = a0 * Ws[j] + a1 * Ws[64 + j] + a2 * Ws[128 + j] + bs[j];
    x1[idx] = v > 0.f ? v : 0.f;
}

// ---------------- tf32 tensor-core GEMM v3 ----------------------------------
// Block 128x128, BK=16, 8 warps (32x64 warp tile), mma.sync m16n8k8 tf32.
// Inputs pre-rounded to tf32 -> mainloop consumes raw bits, zero CVTs.
#define ASTRIDE 20    // (gr*20 + tg) mod 32 covers all 32 banks
#define BSTRIDE 136   // 136 mod 32 = 8; (tg*8 + gr) covers all 32 banks

__device__ __forceinline__ void cp_async16(void* smem_dst, const void* gmem_src) {
    unsigned sa = (unsigned)__cvta_generic_to_shared(smem_dst);
    asm volatile("cp.async.cg.shared.global [%0], [%1], 16;\n"
                 :: "r"(sa), "l"(gmem_src) : "memory");
}

__device__ __forceinline__ void cp_commit() {
    asm volatile("cp.async.commit_group;\n" ::: "memory");
}

template <int NW>
__device__ __forceinline__ void cp_wait() {
    asm volatile("cp.async.wait_group %0;\n" :: "n"(NW) : "memory");
}

__global__ __launch_bounds__(256)
void k_tf32gemm(const float* __restrict__ A, const float* __restrict__ Bm,
                const float* __restrict__ bias, float* __restrict__ C,
                int N, int K) {
    __shared__ __align__(16) float As[2][128 * ASTRIDE];   // 20.0 KB
    __shared__ __align__(16) float Bs[2][16 * BSTRIDE];    // 17.0 KB

    int tid = threadIdx.x;
    int lane = tid & 31;
    int warp = tid >> 5;
    int warpM = warp >> 1;        // 0..3  (32 rows each)
    int warpN = warp & 1;         // 0..1  (64 cols each)
    int rowBase = blockIdx.y * 128;
    int colBase = blockIdx.x * 128;

    // staging coords
    int sArow = tid >> 1;                  // 0..127
    int sAk4  = (tid & 1) * 8;             // 0 or 8 (two float4s)
    int sBrow = tid >> 4;                  // 0..15
    int sBn4  = (tid & 15) * 8;            // 0..120 (two float4s)

    float acc[2][8][4];
#pragma unroll
    for (int m = 0; m < 2; m++)
#pragma unroll
        for (int n = 0; n < 8; n++)
#pragma unroll
            for (int q = 0; q < 4; q++) acc[m][n][q] = 0.f;

    int nt = K >> 4;

    // prologue: stage tile 0
    {
        const float* ga = &A[(size_t)(rowBase + sArow) * K + sAk4];
        cp_async16(&As[0][sArow * ASTRIDE + sAk4], ga);
        cp_async16(&As[0][sArow * ASTRIDE + sAk4 + 4], ga + 4);
        const float* gb = &Bm[(size_t)sBrow * N + colBase + sBn4];
        cp_async16(&Bs[0][sBrow * BSTRIDE + sBn4], gb);
        cp_async16(&Bs[0][sBrow * BSTRIDE + sBn4 + 4], gb + 4);
        cp_commit();
    }

    int gr = lane >> 2;      // 0..7
    int tg = lane & 3;       // 0..3

    for (int t = 0; t < nt; t++) {
        int cur = t & 1;
        if (t + 1 < nt) {
            int nxt = cur ^ 1;
            int k0 = (t + 1) << 4;
            const float* ga = &A[(size_t)(rowBase + sArow) * K + k0 + sAk4];
            cp_async16(&As[nxt][sArow * ASTRIDE + sAk4], ga);
            cp_async16(&As[nxt][sArow * ASTRIDE + sAk4 + 4], ga + 4);
            const float* gb = &Bm[(size_t)(k0 + sBrow) * N + colBase + sBn4];
            cp_async16(&Bs[nxt][sBrow * BSTRIDE + sBn4], gb);
            cp_async16(&Bs[nxt][sBrow * BSTRIDE + sBn4 + 4], gb + 4);
            cp_commit();
            cp_wait<1>();
        } else {
            cp_wait<0>();
        }
        __syncthreads();

#pragma unroll
        for (int ki = 0; ki < 2; ki++) {
            unsigned a[2][4];
#pragma unroll
            for (int m = 0; m < 2; m++) {
                const float* base =
                    &As[cur][((warpM * 2 + m) * 16 + gr) * ASTRIDE + ki * 8 + tg];
                a[m][0] = __float_as_uint(base[0]);
                a[m][1] = __float_as_uint(base[8 * ASTRIDE]);
                a[m][2] = __float_as_uint(base[4]);
                a[m][3] = __float_as_uint(base[8 * ASTRIDE + 4]);
            }
            unsigned b[8][2];
#pragma unroll
            for (int n = 0; n < 8; n++) {
                const float* bp =
                    &Bs[cur][(ki * 8 + tg) * BSTRIDE + warpN * 64 + n * 8 + gr];
                b[n][0] = __float_as_uint(bp[0]);
                b[n][1] = __float_as_uint(bp[4 * BSTRIDE]);
            }
#pragma unroll
            for (int m = 0; m < 2; m++)
#pragma unroll
                for (int n = 0; n < 8; n++) {
                    asm volatile(
                        "mma.sync.aligned.m16n8k8.row.col.f32.tf32.tf32.f32 "
                        "{%0,%1,%2,%3}, {%4,%5,%6,%7}, {%8,%9}, {%0,%1,%2,%3};"
                        : "+f"(acc[m][n][0]), "+f"(acc[m][n][1]),
                          "+f"(acc[m][n][2]), "+f"(acc[m][n][3])
                        : "r"(a[m][0]), "r"(a[m][1]), "r"(a[m][2]), "r"(a[m][3]),
                          "r"(b[n][0]), "r"(b[n][1]));
                }
        }
        __syncthreads();
    }

    // ---- epilogue: bias + relu, float2 stores ----
    int gc = tg * 2;
#pragma unroll
    for (int m = 0; m < 2; m++) {
        int row0 = rowBase + (warpM * 2 + m) * 16 + gr;
#pragma unroll
        for (int n = 0; n < 8; n++) {
            int col = colBase + warpN * 64 + n * 8 + gc;
            float b0 = bias[col], b1 = bias[col + 1];
            float2 v0, v1;
            v0.x = acc[m][n][0] + b0; v0.y = acc[m][n][1] + b1;
            v1.x = acc[m][n][2] + b0; v1.y = acc[m][n][3] + b1;
            v0.x = v0.x > 0.f ? v0.x : 0.f;
            v0.y = v0.y > 0.f ? v0.y : 0.f;
            v1.x = v1.x > 0.f ? v1.x : 0.f;
            v1.y = v1.y > 0.f ? v1.y : 0.f;
            *(float2*)&C[(size_t)row0 * N + col] = v0;
            *(float2*)&C[(size_t)(row0 + 8) * N + col] = v1;
        }
    }
}

// ---------------- pooling + MLP head ----------------------------------------
__global__ void k_pool(const float* __restrict__ x3, float* __restrict__ h) {
    int g = blockIdx.x;
    int f = threadIdx.x;
    const float* base = x3 + (size_t)g * PTS * 512 + f;
    float s = 0.f, m = -INFINITY;
#pragma unroll 8
    for (int n = 0; n < PTS; n++) {
        float v = base[(size_t)n * 512];
        s += v;
        m = fmaxf(m, v);
    }
    h[g * 1024 + f] = s * (1.0f / PTS);
    h[g * 1024 + 512 + f] = m;
}

__global__ void k_mlp1(const float* __restrict__ h, const float* __restrict__ W,
                       const float* __restrict__ b, float* __restrict__ h2) {
    __shared__ float hs[1024];
    int g = blockIdx.x;
    int c = threadIdx.x;
    for (int k = c; k < 1024; k += 512) hs[k] = h[g * 1024 + k];
    __syncthreads();
    float acc = b[c];
#pragma unroll 4
    for (int k = 0; k < 1024; k++) acc += hs[k] * W[k * 512 + c];
    h2[g * 512 + c] = acc > 0.f ? acc : 0.f;
}

__global__ void k_mlp2(const float* __restrict__ h2, const float* __restrict__ W,
                       const float* __restrict__ b, float* __restrict__ out) {
    int idx = blockIdx.x * blockDim.x + threadIdx.x;
    if (idx >= N_GRAPHS * 10) return;
    int g = idx / 10;
    int c = idx % 10;
    float acc = b[c];
    const float* hr = h2 + g * 512;
#pragma unroll 8
    for (int k = 0; k < 512; k++) acc += hr[k] * W[k * 10 + c];
    out[idx] = acc;
}

// ---------------- host orchestration ----------------------------------------
extern "C" void kernel_launch(void* const* d_in, const int* in_sizes, int n_in,
                              void* d_out, int out_size) {
    const float* x   = (const float*)d_in[0];
    const int*   ei  = (const int*)d_in[1];   // int32 (JAX x64-disabled)
    const float* W1  = (const float*)d_in[3];
    const float* b1  = (const float*)d_in[4];
    const float* W2  = (const float*)d_in[5];
    const float* b2  = (const float*)d_in[6];
    const float* W3  = (const float*)d_in[7];
    const float* b3  = (const float*)d_in[8];
    const float* Wm1 = (const float*)d_in[9];
    const float* bm1 = (const float*)d_in[10];
    const float* Wm2 = (const float*)d_in[11];
    const float* bm2 = (const float*)d_in[12];
    float* out = (float*)d_out;

    float *bufA, *bufB, *bufC, *dinv, *ccoef, *w2r, *w3r, *h, *h2;
    int *cnt, *cursor, *tmp, *bsum, *boff, *rowptr, *csrc;
    cudaGetSymbolAddress((void**)&bufA,   g_bufA);
    cudaGetSymbolAddress((void**)&bufB,   g_bufB);
    cudaGetSymbolAddress((void**)&bufC,   g_bufC);
    cudaGetSymbolAddress((void**)&dinv,   g_dinv);
    cudaGetSymbolAddress((void**)&cnt,    g_cnt);
    cudaGetSymbolAddress((void**)&cursor, g_cursor);
    cudaGetSymbolAddress((void**)&tmp,    g_tmp);
    cudaGetSymbolAddress((void**)&bsum,   g_bsum);
    cudaGetSymbolAddress((void**)&boff,   g_boff);
    cudaGetSymbolAddress((void**)&rowptr, g_rowptr);
    cudaGetSymbolAddress((void**)&csrc,   g_csrc);
    cudaGetSymbolAddress((void**)&ccoef,  g_ccoef);
    cudaGetSymbolAddress((void**)&w2r,    g_w2r);
    cudaGetSymbolAddress((void**)&w3r,    g_w3r);
    cudaGetSymbolAddress((void**)&h,      g_h);
    cudaGetSymbolAddress((void**)&h2,     g_h2);

    // ---- CSR build + normalization. Launch index 3 (the one ncu captures)
    // is a small DIAGNOSTIC clone of the v3 GEMM (reads stale-but-deterministic
    // bufB + raw W3; writes bufA rows<1024, fully overwritten by k_gemm1). ----
    k_zero2<<<N_NODES / 256, 256>>>(cnt, cursor);                 // 0
    k_count<<<N_EDGES / 256, 256>>>(ei, cnt);                     // 1
    k_dinv<<<N_NODES / 256, 256>>>(cnt, dinv);                    // 2
    {
        dim3 gprof(512 / 128, 8);
        k_tf32gemm<<<gprof, 256>>>(bufB, W3, b3, bufA, 512, 256); // 3 (profiled)
    }
    k_round<<<64, 256>>>(W2, w2r, 64 * 256);                      // 4
    k_round<<<512, 256>>>(W3, w3r, 256 * 512);                    // 5
    k_scan1<<<64, 1024>>>(cnt, tmp, bsum);                        // 6
    k_scan2<<<1, 64>>>(bsum, boff);                               // 7
    k_scan3<<<N_NODES / 256, 256>>>(tmp, boff, rowptr);           // 8
    k_fill<<<N_EDGES / 256, 256>>>(ei, dinv, rowptr, cursor, csrc, ccoef); // 9

    // ---- layer 1: aggregate F=3 (y0 -> bufB), GEMM 3->64 (x1 -> bufA) ----
    k_agg3<<<N_NODES / 256, 256>>>(rowptr, csrc, ccoef, x, dinv, bufB);
    k_gemm1<<<(N_NODES * 64) / 256, 256>>>(bufB, W1, b1, bufA);

    // ---- layer 2: aggregate F=64 (bufA -> bufC, tf32-rounded),
    //      tf32 GEMM 64->256 (-> bufA) ----
    k_agg64<<<(N_NODES * 32) / 256, 256>>>(rowptr, csrc, ccoef, bufA, dinv, bufC);
    {
        dim3 grid(256 / 128, N_NODES / 128);
        k_tf32gemm<<<grid, 256>>>(bufC, w2r, b2, bufA, 256, 64);
    }

    // ---- layer 3: aggregate F=256 (bufA -> bufB, tf32-rounded),
    //      tf32 GEMM 256->512 (-> bufC) ----
    k_agg256<<<(N_NODES * 32) / 256, 256>>>(rowptr, csrc, ccoef, bufA, dinv, bufB);
    {
        dim3 grid(512 / 128, N_NODES / 128);
        k_tf32gemm<<<grid, 256>>>(bufB, w3r, b3, bufC, 512, 256);
    }

    // ---- pooling + MLP head ----
    k_pool<<<N_GRAPHS, 512>>>(bufC, h);
    k_mlp1<<<N_GRAPHS, 512>>>(h, Wm1, bm1, h2);
    k_mlp2<<<(N_GRAPHS * 10 + 255) / 256, 256>>>(h2, Wm2, bm2, out);

    (void)in_sizes; (void)n_in; (void)out_size;
}

// round 17
// speedup vs baseline: 1.5147x; 1.0763x over previous
#include <cuda_runtime.h>
#include <math.h>

#define N_NODES 65536
#define N_EDGES 524288
#define N_GRAPHS 64
#define PTS 1024
#define FMAX 512

// ---------------- scratch (device globals: no allocation allowed) ----------
__device__ float g_bufA[(size_t)N_NODES * FMAX];
__device__ float g_bufB[(size_t)N_NODES * FMAX];
__device__ float g_bufC[(size_t)N_NODES * FMAX];
__device__ float g_dinv[N_NODES];
__device__ int   g_cnt[N_NODES];
__device__ int   g_cursor[N_NODES];
__device__ int   g_tmp[N_NODES];
__device__ int   g_bsum[64];
__device__ int   g_boff[64];
__device__ int   g_rowptr[N_NODES + 1];
__device__ int   g_csrc[N_EDGES];
__device__ float g_ccoef[N_EDGES];
__device__ float g_w2r[64 * 256];      // tf32-pre-rounded W2
__device__ float g_w3r[256 * 512];     // tf32-pre-rounded W3
__device__ float g_h[N_GRAPHS * 1024];
__device__ float g_h2[N_GRAPHS * 512];

// ---------------- tf32 rounding helper --------------------------------------
__device__ __forceinline__ float roundtf32(float x) {
    unsigned u;
    asm("cvt.rna.tf32.f32 %0, %1;" : "=r"(u) : "f"(x));
    return __uint_as_float(u);
}

// ---------------- counters / normalization ---------------------------------
__global__ void k_zero2(int* cnt, int* cursor) {
    int i = blockIdx.x * blockDim.x + threadIdx.x;
    if (i < N_NODES) { cnt[i] = 0; cursor[i] = 0; }
}

__global__ void k_count(const int* __restrict__ ei, int* __restrict__ cnt) {
    int e = blockIdx.x * blockDim.x + threadIdx.x;
    if (e < N_EDGES) atomicAdd(&cnt[ei[N_EDGES + e]], 1);
}

__global__ void k_dinv(const int* __restrict__ cnt, float* __restrict__ dinv) {
    int i = blockIdx.x * blockDim.x + threadIdx.x;
    if (i < N_NODES) dinv[i] = rsqrtf((float)(cnt[i] + 1));   // +1 self-loop
}

// ---------------- pre-round W2 and W3 to tf32 (single launch) ---------------
__global__ void k_round2(const float* __restrict__ W2, float* __restrict__ w2r,
                         const float* __restrict__ W3, float* __restrict__ w3r) {
    int i = blockIdx.x * blockDim.x + threadIdx.x;
    if (i < 64 * 256) w2r[i] = roundtf32(W2[i]);
    if (i < 256 * 512) w3r[i] = roundtf32(W3[i]);
}

// ---------------- exclusive scan of cnt -> rowptr ---------------------------
__global__ void k_scan1(const int* __restrict__ cnt, int* __restrict__ tmp,
                        int* __restrict__ bsum) {
    __shared__ int s[1024];
    int t = threadIdx.x;
    int i = blockIdx.x * 1024 + t;
    s[t] = cnt[i];
    __syncthreads();
    for (int off = 1; off < 1024; off <<= 1) {
        int x = (t >= off) ? s[t - off] : 0;
        __syncthreads();
        s[t] += x;
        __syncthreads();
    }
    tmp[i] = s[t];
    if (t == 1023) bsum[blockIdx.x] = s[t];
}

__global__ void k_scan2(const int* __restrict__ bsum, int* __restrict__ boff) {
    __shared__ int s[64];
    int t = threadIdx.x;
    s[t] = bsum[t];
    __syncthreads();
    for (int off = 1; off < 64; off <<= 1) {
        int x = (t >= off) ? s[t - off] : 0;
        __syncthreads();
        s[t] += x;
        __syncthreads();
    }
    boff[t] = (t == 0) ? 0 : s[t - 1];
}

__global__ void k_scan3(const int* __restrict__ tmp, const int* __restrict__ boff,
                        int* __restrict__ rowptr) {
    int i = blockIdx.x * blockDim.x + threadIdx.x;
    if (i < N_NODES) {
        rowptr[i + 1] = tmp[i] + boff[i >> 10];
        if (i == 0) rowptr[0] = 0;
    }
}

__global__ void k_fill(const int* __restrict__ ei, const float* __restrict__ dinv,
                       const int* __restrict__ rowptr, int* __restrict__ cursor,
                       int* __restrict__ csrc, float* __restrict__ ccoef) {
    int e = blockIdx.x * blockDim.x + threadIdx.x;
    if (e >= N_EDGES) return;
    int r = ei[e];
    int c = ei[N_EDGES + e];
    int slot = rowptr[c] + atomicAdd(&cursor[c], 1);
    csrc[slot] = r;
    ccoef[slot] = dinv[r] * dinv[c];
}

// ---------------- CSR aggregations ------------------------------------------
__global__ void k_agg3(const int* __restrict__ rowptr, const int* __restrict__ csrc,
                       const float* __restrict__ ccoef, const float* __restrict__ x,
                       const float* __restrict__ dinv, float* __restrict__ y) {
    int i = blockIdx.x * blockDim.x + threadIdx.x;
    if (i >= N_NODES) return;
    float d = dinv[i];
    float d2 = d * d;
    float a0 = x[i * 3 + 0] * d2, a1 = x[i * 3 + 1] * d2, a2 = x[i * 3 + 2] * d2;
    int beg = rowptr[i], end = rowptr[i + 1];
    for (int j = beg; j < end; j++) {
        int s = csrc[j];
        float w = ccoef[j];
        a0 += x[s * 3 + 0] * w;
        a1 += x[s * 3 + 1] * w;
        a2 += x[s * 3 + 2] * w;
    }
    y[i * 3 + 0] = a0;
    y[i * 3 + 1] = a1;
    y[i * 3 + 2] = a2;
}

// Output rounded to tf32 (consumed raw by the tensor-core GEMM)
__global__ void k_agg64(const int* __restrict__ rowptr, const int* __restrict__ csrc,
                        const float* __restrict__ ccoef, const float* __restrict__ xw,
                        const float* __restrict__ dinv, float* __restrict__ out) {
    int w = (blockIdx.x * blockDim.x + threadIdx.x) >> 5;
    int lane = threadIdx.x & 31;
    if (w >= N_NODES) return;
    float d = dinv[w];
    float d2 = d * d;
    float2 a = ((const float2*)&xw[(size_t)w * 64])[lane];
    a.x *= d2; a.y *= d2;
    int beg = rowptr[w], end = rowptr[w + 1];
    for (int j = beg; j < end; j++) {
        int s = csrc[j];
        float c = ccoef[j];
        float2 v = ((const float2*)&xw[(size_t)s * 64])[lane];
        a.x += v.x * c;
        a.y += v.y * c;
    }
    a.x = roundtf32(a.x);
    a.y = roundtf32(a.y);
    ((float2*)&out[(size_t)w * 64])[lane] = a;
}

__global__ void k_agg256(const int* __restrict__ rowptr, const int* __restrict__ csrc,
                         const float* __restrict__ ccoef, const float* __restrict__ xw,
                         const float* __restrict__ dinv, float* __restrict__ out) {
    int w = (blockIdx.x * blockDim.x + threadIdx.x) >> 5;
    int lane = threadIdx.x & 31;
    if (w >= N_NODES) return;
    float d = dinv[w];
    float d2 = d * d;
    const float4* selfrow = (const float4*)&xw[(size_t)w * 256];
    float4 a0 = selfrow[lane];
    float4 a1 = selfrow[lane + 32];
    a0.x *= d2; a0.y *= d2; a0.z *= d2; a0.w *= d2;
    a1.x *= d2; a1.y *= d2; a1.z *= d2; a1.w *= d2;
    int beg = rowptr[w], end = rowptr[w + 1];
    int j = beg;
    for (; j + 2 <= end; j += 2) {
        int s0 = csrc[j], s1 = csrc[j + 1];
        float c0 = ccoef[j], c1 = ccoef[j + 1];
        const float4* r0 = (const float4*)&xw[(size_t)s0 * 256];
        const float4* r1 = (const float4*)&xw[(size_t)s1 * 256];
        float4 u0 = r0[lane], u1 = r0[lane + 32];
        float4 v0 = r1[lane], v1 = r1[lane + 32];
        a0.x += u0.x * c0; a0.y += u0.y * c0; a0.z += u0.z * c0; a0.w += u0.w * c0;
        a1.x += u1.x * c0; a1.y += u1.y * c0; a1.z += u1.z * c0; a1.w += u1.w * c0;
        a0.x += v0.x * c1; a0.y += v0.y * c1; a0.z += v0.z * c1; a0.w += v0.w * c1;
        a1.x += v1.x * c1; a1.y += v1.y * c1; a1.z += v1.z * c1; a1.w += v1.w * c1;
    }
    if (j < end) {
        int s = csrc[j];
        float c = ccoef[j];
        const float4* row = (const float4*)&xw[(size_t)s * 256];
        float4 v0 = row[lane];
        float4 v1 = row[lane + 32];
        a0.x += v0.x * c; a0.y += v0.y * c; a0.z += v0.z * c; a0.w += v0.w * c;
        a1.x += v1.x * c; a1.y += v1.y * c; a1.z += v1.z * c; a1.w += v1.w * c;
    }
    a0.x = roundtf32(a0.x); a0.y = roundtf32(a0.y);
    a0.z = roundtf32(a0.z); a0.w = roundtf32(a0.w);
    a1.x = roundtf32(a1.x); a1.y = roundtf32(a1.y);
    a1.z = roundtf32(a1.z); a1.w = roundtf32(a1.w);
    float4* o = (float4*)&out[(size_t)w * 256];
    o[lane] = a0;
    o[lane + 32] = a1;
}

// ---------------- layer-1 GEMM (K=3, N=64) ----------------------------------
__global__ void k_gemm1(const float* __restrict__ y0, const float* __restrict__ W,
                        const float* __restrict__ bias, float* __restrict__ x1) {
    __shared__ float Ws[192];
    __shared__ float bs[64];
    int t = threadIdx.x;
    if (t < 192) Ws[t] = W[t];
    if (t < 64) bs[t] = bias[t];
    __syncthreads();
    int idx = blockIdx.x * blockDim.x + t;
    int i = idx >> 6;
    int j = idx & 63;
    float a0 = y0[i * 3 + 0], a1 = y0[i * 3 + 1], a2 = y0[i * 3 + 2];
    float v = a0 * Ws[j] + a1 * Ws[64 + j] + a2 * Ws[128 + j] + bs[j];
    x1[idx] = v > 0.f ? v : 0.f;
}

// ---------------- tf32 tensor-core GEMM v4 ----------------------------------
// Block 128x256, BK=16, 8 warps (warp tile 64x64), mma.sync m16n8k8 tf32.
// XOR-swizzled smem (no padding, exactly 48KB), cp.async double buffering.
// LDS:MMA = 1.0 per k8-step (16 a-LDS + 16 b-LDS feed 32 MMAs per warp).
__device__ __forceinline__ void cp_async16(void* smem_dst, const void* gmem_src) {
    unsigned sa = (unsigned)__cvta_generic_to_shared(smem_dst);
    asm volatile("cp.async.cg.shared.global [%0], [%1], 16;\n"
                 :: "r"(sa), "l"(gmem_src) : "memory");
}

__device__ __forceinline__ void cp_commit() {
    asm volatile("cp.async.commit_group;\n" ::: "memory");
}

template <int NW>
__device__ __forceinline__ void cp_wait() {
    asm volatile("cp.async.wait_group %0;\n" :: "n"(NW) : "memory");
}

__global__ __launch_bounds__(256)
void k_tf32gemm(const float* __restrict__ A, const float* __restrict__ Bm,
                const float* __restrict__ bias, float* __restrict__ C,
                int N, int K) {
    __shared__ __align__(16) float As[2][128 * 16];   // 16 KB
    __shared__ __align__(16) float Bs[2][16 * 256];   // 32 KB

    int tid = threadIdx.x;
    int lane = tid & 31;
    int warp = tid >> 5;
    int warpM = warp >> 2;        // 0..1  (64 rows each)
    int warpN = warp & 3;         // 0..3  (64 cols each)
    int rowBase = blockIdx.y * 128;
    int colBase = blockIdx.x * 256;

    // staging coords
    int sArow = tid >> 2;                  // 0..63 (+64 via f+256)
    int sAc4  = (tid & 3) * 4;             // 0,4,8,12
    int sBrow4[4], sBcol4[4];
#pragma unroll
    for (int i = 0; i < 4; i++) {
        int f = tid + i * 256;
        sBrow4[i] = f >> 6;                // 0..15
        sBcol4[i] = (f & 63) * 4;          // 0..252
    }

    float acc[4][8][4];
#pragma unroll
    for (int m = 0; m < 4; m++)
#pragma unroll
        for (int n = 0; n < 8; n++)
#pragma unroll
            for (int q = 0; q < 4; q++) acc[m][n][q] = 0.f;

    int nt = K >> 4;

    // A smem phys col = c ^ (((row>>1)&3)<<2); B smem phys col = c ^ ((row&3)<<3)
    auto stageA = [&](int buf, int k0) {
#pragma unroll
        for (int i = 0; i < 2; i++) {
            int row = sArow + i * 64;
            int phys = row * 16 + (sAc4 ^ ((((unsigned)row >> 1) & 3) << 2));
            cp_async16(&As[buf][phys], &A[(size_t)(rowBase + row) * K + k0 + sAc4]);
        }
#pragma unroll
        for (int i = 0; i < 4; i++) {
            int brow = sBrow4[i];
            int phys = brow * 256 + (sBcol4[i] ^ ((brow & 3) << 3));
            cp_async16(&Bs[buf][phys], &Bm[(size_t)(k0 + brow) * N + colBase + sBcol4[i]]);
        }
        cp_commit();
    };

    stageA(0, 0);

    int gr = lane >> 2;      // 0..7
    int tg = lane & 3;       // 0..3
    int ga = ((gr >> 1) & 3) << 2;   // A col swizzle (depends on row bits 1-2 = gr bits 1-2)
    int gb = tg << 3;                // B col swizzle (row&3 = tg)

    for (int t = 0; t < nt; t++) {
        int cur = t & 1;
        if (t + 1 < nt) {
            stageA(cur ^ 1, (t + 1) << 4);
            cp_wait<1>();
        } else {
            cp_wait<0>();
        }
        __syncthreads();

#pragma unroll
        for (int ki = 0; ki < 2; ki++) {
            int col0 = (ki * 8 + tg) ^ ga;
            int col1 = (ki * 8 + tg + 4) ^ ga;
            unsigned a[4][4];
#pragma unroll
            for (int m = 0; m < 4; m++) {
                const float* p = &As[cur][(warpM * 64 + m * 16 + gr) * 16];
                a[m][0] = __float_as_uint(p[col0]);
                a[m][1] = __float_as_uint(p[128 + col0]);   // +8 rows
                a[m][2] = __float_as_uint(p[col1]);
                a[m][3] = __float_as_uint(p[128 + col1]);
            }
            unsigned b[8][2];
#pragma unroll
            for (int n = 0; n < 8; n++) {
                int col = (warpN * 64 + n * 8 + gr) ^ gb;
                b[n][0] = __float_as_uint(Bs[cur][(ki * 8 + tg) * 256 + col]);
                b[n][1] = __float_as_uint(Bs[cur][(ki * 8 + tg + 4) * 256 + col]);
            }
#pragma unroll
            for (int m = 0; m < 4; m++)
#pragma unroll
                for (int n = 0; n < 8; n++) {
                    asm volatile(
                        "mma.sync.aligned.m16n8k8.row.col.f32.tf32.tf32.f32 "
                        "{%0,%1,%2,%3}, {%4,%5,%6,%7}, {%8,%9}, {%0,%1,%2,%3};"
                        : "+f"(acc[m][n][0]), "+f"(acc[m][n][1]),
                          "+f"(acc[m][n][2]), "+f"(acc[m][n][3])
                        : "r"(a[m][0]), "r"(a[m][1]), "r"(a[m][2]), "r"(a[m][3]),
                          "r"(b[n][0]), "r"(b[n][1]));
                }
        }
        __syncthreads();
    }

    // ---- epilogue: bias + relu, float2 stores ----
    int gc = tg * 2;
#pragma unroll
    for (int m = 0; m < 4; m++) {
        int row0 = rowBase + warpM * 64 + m * 16 + gr;
#pragma unroll
        for (int n = 0; n < 8; n++) {
            int col = colBase + warpN * 64 + n * 8 + gc;
            float b0 = bias[col], b1 = bias[col + 1];
            float2 v0, v1;
            v0.x = acc[m][n][0] + b0; v0.y = acc[m][n][1] + b1;
            v1.x = acc[m][n][2] + b0; v1.y = acc[m][n][3] + b1;
            v0.x = v0.x > 0.f ? v0.x : 0.f;
            v0.y = v0.y > 0.f ? v0.y : 0.f;
            v1.x = v1.x > 0.f ? v1.x : 0.f;
            v1.y = v1.y > 0.f ? v1.y : 0.f;
            *(float2*)&C[(size_t)row0 * N + col] = v0;
            *(float2*)&C[(size_t)(row0 + 8) * N + col] = v1;
        }
    }
}

// ---------------- pooling + MLP head ----------------------------------------
__global__ void k_pool(const float* __restrict__ x3, float* __restrict__ h) {
    int g = blockIdx.x;
    int f = threadIdx.x;
    const float* base = x3 + (size_t)g * PTS * 512 + f;
    float s = 0.f, m = -INFINITY;
#pragma unroll 8
    for (int n = 0; n < PTS; n++) {
        float v = base[(size_t)n * 512];
        s += v;
        m = fmaxf(m, v);
    }
    h[g * 1024 + f] = s * (1.0f / PTS);
    h[g * 1024 + 512 + f] = m;
}

__global__ void k_mlp1(const float* __restrict__ h, const float* __restrict__ W,
                       const float* __restrict__ b, float* __restrict__ h2) {
    __shared__ float hs[1024];
    int g = blockIdx.x;
    int c = threadIdx.x;
    for (int k = c; k < 1024; k += 512) hs[k] = h[g * 1024 + k];
    __syncthreads();
    float acc = b[c];
#pragma unroll 4
    for (int k = 0; k < 1024; k++) acc += hs[k] * W[k * 512 + c];
    h2[g * 512 + c] = acc > 0.f ? acc : 0.f;
}

__global__ void k_mlp2(const float* __restrict__ h2, const float* __restrict__ W,
                       const float* __restrict__ b, float* __restrict__ out) {
    int idx = blockIdx.x * blockDim.x + threadIdx.x;
    if (idx >= N_GRAPHS * 10) return;
    int g = idx / 10;
    int c = idx % 10;
    float acc = b[c];
    const float* hr = h2 + g * 512;
#pragma unroll 8
    for (int k = 0; k < 512; k++) acc += hr[k] * W[k * 10 + c];
    out[idx] = acc;
}

// ---------------- host orchestration ----------------------------------------
extern "C" void kernel_launch(void* const* d_in, const int* in_sizes, int n_in,
                              void* d_out, int out_size) {
    const float* x   = (const float*)d_in[0];
    const int*   ei  = (const int*)d_in[1];   // int32 (JAX x64-disabled)
    const float* W1  = (const float*)d_in[3];
    const float* b1  = (const float*)d_in[4];
    const float* W2  = (const float*)d_in[5];
    const float* b2  = (const float*)d_in[6];
    const float* W3  = (const float*)d_in[7];
    const float* b3  = (const float*)d_in[8];
    const float* Wm1 = (const float*)d_in[9];
    const float* bm1 = (const float*)d_in[10];
    const float* Wm2 = (const float*)d_in[11];
    const float* bm2 = (const float*)d_in[12];
    float* out = (float*)d_out;

    float *bufA, *bufB, *bufC, *dinv, *ccoef, *w2r, *w3r, *h, *h2;
    int *cnt, *cursor, *tmp, *bsum, *boff, *rowptr, *csrc;
    cudaGetSymbolAddress((void**)&bufA,   g_bufA);
    cudaGetSymbolAddress((void**)&bufB,   g_bufB);
    cudaGetSymbolAddress((void**)&bufC,   g_bufC);
    cudaGetSymbolAddress((void**)&dinv,   g_dinv);
    cudaGetSymbolAddress((void**)&cnt,    g_cnt);
    cudaGetSymbolAddress((void**)&cursor, g_cursor);
    cudaGetSymbolAddress((void**)&tmp,    g_tmp);
    cudaGetSymbolAddress((void**)&bsum,   g_bsum);
    cudaGetSymbolAddress((void**)&boff,   g_boff);
    cudaGetSymbolAddress((void**)&rowptr, g_rowptr);
    cudaGetSymbolAddress((void**)&csrc,   g_csrc);
    cudaGetSymbolAddress((void**)&ccoef,  g_ccoef);
    cudaGetSymbolAddress((void**)&w2r,    g_w2r);
    cudaGetSymbolAddress((void**)&w3r,    g_w3r);
    cudaGetSymbolAddress((void**)&h,      g_h);
    cudaGetSymbolAddress((void**)&h2,     g_h2);

    // ---- CSR build + normalization (diagnostic removed) ----
    k_zero2<<<N_NODES / 256, 256>>>(cnt, cursor);
    k_count<<<N_EDGES / 256, 256>>>(ei, cnt);
    k_dinv<<<N_NODES / 256, 256>>>(cnt, dinv);
    k_round2<<<(256 * 512 + 255) / 256, 256>>>(W2, w2r, W3, w3r);
    k_scan1<<<64, 1024>>>(cnt, tmp, bsum);
    k_scan2<<<1, 64>>>(bsum, boff);
    k_scan3<<<N_NODES / 256, 256>>>(tmp, boff, rowptr);
    k_fill<<<N_EDGES / 256, 256>>>(ei, dinv, rowptr, cursor, csrc, ccoef);

    // ---- layer 1: aggregate F=3 (y0 -> bufB), GEMM 3->64 (x1 -> bufA) ----
    k_agg3<<<N_NODES / 256, 256>>>(rowptr, csrc, ccoef, x, dinv, bufB);
    k_gemm1<<<(N_NODES * 64) / 256, 256>>>(bufB, W1, b1, bufA);

    // ---- layer 2: aggregate F=64 (bufA -> bufC, tf32-rounded),
    //      tf32 GEMM 64->256 (-> bufA) ----
    k_agg64<<<(N_NODES * 32) / 256, 256>>>(rowptr, csrc, ccoef, bufA, dinv, bufC);
    {
        dim3 grid(256 / 256, N_NODES / 128);
        k_tf32gemm<<<grid, 256>>>(bufC, w2r, b2, bufA, 256, 64);
    }

    // ---- layer 3: aggregate F=256 (bufA -> bufB, tf32-rounded),
    //      tf32 GEMM 256->512 (-> bufC) ----
    k_agg256<<<(N_NODES * 32) / 256, 256>>>(rowptr, csrc, ccoef, bufA, dinv, bufB);
    {
        dim3 grid(512 / 256, N_NODES / 128);
        k_tf32gemm<<<grid, 256>>>(bufB, w3r, b3, bufC, 512, 256);
    }

    // ---- pooling + MLP head ----
    k_pool<<<N_GRAPHS, 512>>>(bufC, h);
    k_mlp1<<<N_GRAPHS, 512>>>(h, Wm1, bm1, h2);
    k_mlp2<<<(N_GRAPHS * 10 + 255) / 256, 256>>>(h2, Wm2, bm2, out);

    (void)in_sizes; (void)n_in; (void)out_size;
}